// round 1
// baseline (speedup 1.0000x reference)
#include <cuda_runtime.h>
#include <math.h>
#include <math_constants.h>

// Problem constants
#define BB    2
#define CC    256
#define NTOK  32768      // 32*32*32
#define SS    256
#define TDIM  512
#define NHD   8
#define HDIM  32

// ---------------- scratch (single __device__ array, no allocations) ----------------
#define OFF_H1    0                         // [B*S*256]      = 131072
#define OFF_KRAW  (OFF_H1   + 131072)       // [B*S*C]
#define OFF_VRAW  (OFF_KRAW + 131072)
#define OFF_PHASE (OFF_VRAW + 131072)
#define OFF_KROT  (OFF_PHASE+ 131072)       // [B,NH,S,HD]
#define OFF_VT    (OFF_KROT + 131072)
#define OFF_Q     (OFF_VT   + 131072)       // [B,N,C] = 16777216
#define OFF_AO    (OFF_Q    + 16777216)     // [B,N,C]
#define OFF_INVF  (OFF_AO   + 16777216)     // [32]
#define SCR_TOTAL (OFF_INVF + 32)

__device__ float g_scr[SCR_TOTAL];

// ---------------- rope inverse-frequency table ----------------
__global__ void init_invf_kernel() {
    int d = threadIdx.x;
    if (d < 32) {
        float e;
        if (d < 10)       e = (float)(2 * (d % 5)) / 10.f;        // z section (zd=10)
        else if (d < 20)  e = (float)(2 * ((d - 10) % 5)) / 10.f; // y section (yd=10)
        else              e = (float)(2 * ((d - 20) % 6)) / 12.f; // x section (xd=12)
        g_scr[OFF_INVF + d] = powf(10000.f, -e);
    }
}

// ---------------- small row-major GEMM (text side): Y = act(A@W + b) ----------------
// A[M,K] row-major, W[K,N], Y[M,N]. BM=BN=64, BK=16, 256 threads, 4x4 micro-tile.
template <int ACT>
__global__ void gemm_rm_kernel(const float* __restrict__ A, const float* __restrict__ W,
                               const float* __restrict__ bias, float* __restrict__ Y,
                               int M, int K, int N) {
    __shared__ float As[16 * 65];
    __shared__ float Ws[16 * 64];
    int t = threadIdx.x;
    int tx = t & 15, ty = t >> 4;
    int m0 = blockIdx.y * 64, j0 = blockIdx.x * 64;
    float acc[4][4] = {};
    for (int k0 = 0; k0 < K; k0 += 16) {
        {
            int m = t >> 2, kq = (t & 3) * 4;
            float4 av = *(const float4*)&A[(size_t)(m0 + m) * K + k0 + kq];
            As[(kq + 0) * 65 + m] = av.x;
            As[(kq + 1) * 65 + m] = av.y;
            As[(kq + 2) * 65 + m] = av.z;
            As[(kq + 3) * 65 + m] = av.w;
            int kk = t >> 4, j4 = (t & 15) * 4;
            *(float4*)&Ws[kk * 64 + j4] = *(const float4*)&W[(size_t)(k0 + kk) * N + j0 + j4];
        }
        __syncthreads();
        #pragma unroll
        for (int kk = 0; kk < 16; kk++) {
            float a[4], w[4];
            #pragma unroll
            for (int i = 0; i < 4; i++) a[i] = As[kk * 65 + ty * 4 + i];
            #pragma unroll
            for (int j = 0; j < 4; j++) w[j] = Ws[kk * 64 + tx + 16 * j];
            #pragma unroll
            for (int i = 0; i < 4; i++)
                #pragma unroll
                for (int j = 0; j < 4; j++) acc[i][j] += a[i] * w[j];
        }
        __syncthreads();
    }
    #pragma unroll
    for (int j = 0; j < 4; j++) {
        int jj = j0 + tx + 16 * j;
        float bv = bias[jj];
        #pragma unroll
        for (int i = 0; i < 4; i++) {
            float v = acc[i][j] + bv;
            if (ACT == 1) v = 0.5f * v * (1.f + erff(v * 0.70710678118654752f));  // exact GELU
            Y[(size_t)(m0 + ty * 4 + i) * N + jj] = v;
        }
    }
}

// ---------------- text rope + [B,S,NH,HD] -> [B,NH,S,HD] transpose ----------------
__global__ void text_rope_kernel() {
    int idx = blockIdx.x * blockDim.x + threadIdx.x;  // < B*S*NH*16 = 65536
    int p = idx & 15;
    int h = (idx >> 4) & 7;
    int s = (idx >> 7) & 255;
    int b = idx >> 15;
    const float* kraw = g_scr + OFF_KRAW;
    const float* vraw = g_scr + OFF_VRAW;
    const float* ph   = g_scr + OFF_PHASE;
    float* krot = g_scr + OFF_KROT;
    float* vt   = g_scr + OFF_VT;
    int base = (b * SS + s) * CC + h * HDIM;
    int out  = ((b * NHD + h) * SS + s) * HDIM;
    float k0 = kraw[base + p], k1 = kraw[base + p + 16];
    float p0 = ph[base + p],   p1 = ph[base + p + 16];
    float c0, s0, c1, s1;
    sincosf(p0, &s0, &c0);
    sincosf(p1, &s1, &c1);
    krot[out + p]      = k0 * c0 - k1 * s0;
    krot[out + p + 16] = k1 * c1 + k0 * s1;
    vt[out + p]        = vraw[base + p];
    vt[out + p + 16]   = vraw[base + p + 16];
}

// ---------------- Q projection: Q[b,n,j] = sum_c fv[b,c,n] * W[c,j] + bias[j] ----------------
// A^T GEMM, 128x128x8 tile, 256 threads, 8x8 micro-tile. A's n-contiguous layout maps
// directly to As[k][m] (no transpose needed on load).
__global__ void qproj_kernel(const float* __restrict__ A, const float* __restrict__ W,
                             const float* __restrict__ bias) {
    __shared__ float As[8 * 128];
    __shared__ float Ws[8 * 128];
    float* Y = g_scr + OFF_Q;
    int b = blockIdx.z;
    int n0 = blockIdx.y * 128, j0 = blockIdx.x * 128;
    int t = threadIdx.x;
    int tx = t & 15, ty = t >> 4;
    const float* Ab = A + (size_t)b * CC * NTOK;
    float acc[8][8] = {};
    int lk = t >> 5, lc = (t & 31) * 4;
    for (int k0 = 0; k0 < CC; k0 += 8) {
        *(float4*)&As[lk * 128 + lc] = *(const float4*)&Ab[(size_t)(k0 + lk) * NTOK + n0 + lc];
        *(float4*)&Ws[lk * 128 + lc] = *(const float4*)&W[(size_t)(k0 + lk) * CC + j0 + lc];
        __syncthreads();
        #pragma unroll
        for (int kk = 0; kk < 8; kk++) {
            float a[8], w[8];
            *(float4*)&a[0] = *(float4*)&As[kk * 128 + ty * 4];
            *(float4*)&a[4] = *(float4*)&As[kk * 128 + 64 + ty * 4];
            *(float4*)&w[0] = *(float4*)&Ws[kk * 128 + tx * 4];
            *(float4*)&w[4] = *(float4*)&Ws[kk * 128 + 64 + tx * 4];
            #pragma unroll
            for (int i = 0; i < 8; i++)
                #pragma unroll
                for (int j = 0; j < 8; j++) acc[i][j] += a[i] * w[j];
        }
        __syncthreads();
    }
    float4 b1 = *(const float4*)&bias[j0 + tx * 4];
    float4 b2 = *(const float4*)&bias[j0 + 64 + tx * 4];
    #pragma unroll
    for (int i = 0; i < 8; i++) {
        int m = n0 + ((i < 4) ? (ty * 4 + i) : (64 + ty * 4 + i - 4));
        float4 v1 = make_float4(acc[i][0] + b1.x, acc[i][1] + b1.y, acc[i][2] + b1.z, acc[i][3] + b1.w);
        float4 v2 = make_float4(acc[i][4] + b2.x, acc[i][5] + b2.y, acc[i][6] + b2.z, acc[i][7] + b2.w);
        float* yp = Y + ((size_t)b * NTOK + m) * CC;
        *(float4*)&yp[j0 + tx * 4]      = v1;
        *(float4*)&yp[j0 + 64 + tx * 4] = v2;
    }
}

// ---------------- 3D rope on Q, in-place (one thread owns pair (p, p+16)) ----------------
__global__ void q_rope_kernel() {
    int idx = blockIdx.x * blockDim.x + threadIdx.x;  // < 2*32768*8*16 = 8388608
    int p = idx & 15;
    int h = (idx >> 4) & 7;
    int n = (idx >> 7) & 32767;
    int b = idx >> 22;
    float* q = g_scr + OFF_Q;
    const float* invf = g_scr + OFF_INVF;
    int wx = n & 31, hy = (n >> 5) & 31, dz = n >> 10;
    // p in [0,16): d<10 -> z pos, 10..15 -> y pos
    float pos0 = (p < 10) ? (float)dz : (float)hy;
    float f0 = pos0 * invf[p];
    int d1 = p + 16;  // 16..19 -> y pos, 20..31 -> x pos
    float pos1 = (d1 < 20) ? (float)hy : (float)wx;
    float f1 = pos1 * invf[d1];
    size_t base = ((size_t)b * NTOK + n) * CC + h * HDIM;
    float q0 = q[base + p], q1 = q[base + p + 16];
    float c0, s0, c1, s1;
    sincosf(f0, &s0, &c0);
    sincosf(f1, &s1, &c1);
    q[base + p]      = q0 * c0 - q1 * s0;
    q[base + p + 16] = q1 * c1 + q0 * s1;
}

// ---------------- attention: per (b,h), 64 tokens/block; K,V,P fully in smem ----------------
#define ATT_SMEM_FLOATS (64*33 + 256*33 + 256*34 + 256*68 + 256 + 256)
__global__ void attn_kernel() {
    extern __shared__ float sm[];
    float* Qs   = sm;                 // [64][33]
    float* Ks   = Qs + 64 * 33;       // [256][33]
    float* Vs   = Ks + 256 * 33;      // [256][34]
    float* Pt   = Vs + 256 * 34;      // [256][68]  (P transposed: [s][m], padded for float4)
    float* Pm   = Pt + 256 * 68;      // [4][64] partial row max
    float* Psum = Pm + 256;           // [4][64] partial row sum
    const float* q    = g_scr + OFF_Q;
    const float* krot = g_scr + OFF_KROT;
    const float* vt   = g_scr + OFF_VT;
    float* ao = g_scr + OFF_AO;
    int b = blockIdx.z, h = blockIdx.y;
    int n0 = blockIdx.x * 64;
    int t = threadIdx.x;

    for (int idx = t; idx < 64 * 32; idx += 256) {
        int tok = idx >> 5, d = idx & 31;
        Qs[tok * 33 + d] = q[((size_t)b * NTOK + n0 + tok) * CC + h * HDIM + d];
    }
    size_t kvbase = (size_t)(b * NHD + h) * SS * HDIM;
    for (int idx = t; idx < 256 * 32; idx += 256) {
        int s = idx >> 5, d = idx & 31;
        Ks[s * 33 + d] = krot[kvbase + idx];
        Vs[s * 34 + d] = vt[kvbase + idx];
    }
    __syncthreads();

    // Phase A: scores[64 x 256] = Q @ K^T * scale, written transposed into Pt[s][m]
    int tx = t & 15, ty = t >> 4;
    const float scale = 0.17677669529663687f;  // 32^-0.5
    #pragma unroll 1
    for (int sc = 0; sc < 4; sc++) {
        float acc[4][4] = {};
        #pragma unroll 8
        for (int d = 0; d < 32; d++) {
            float qv[4], kv[4];
            #pragma unroll
            for (int i = 0; i < 4; i++) qv[i] = Qs[(ty * 4 + i) * 33 + d];
            #pragma unroll
            for (int j = 0; j < 4; j++) kv[j] = Ks[(sc * 64 + tx + 16 * j) * 33 + d];
            #pragma unroll
            for (int i = 0; i < 4; i++)
                #pragma unroll
                for (int j = 0; j < 4; j++) acc[i][j] += qv[i] * kv[j];
        }
        #pragma unroll
        for (int j = 0; j < 4; j++)
            #pragma unroll
            for (int i = 0; i < 4; i++)
                Pt[(sc * 64 + tx + 16 * j) * 68 + ty * 4 + i] = acc[i][j] * scale;
    }
    __syncthreads();

    // Softmax over s: thread owns (row m = t&63, quarter qd = t>>6); Z folded into phase B
    {
        int m = t & 63, qd = t >> 6;
        float mx = -CUDART_INF_F;
        #pragma unroll 4
        for (int k = 0; k < 64; k++) mx = fmaxf(mx, Pt[(qd * 64 + k) * 68 + m]);
        Pm[qd * 64 + m] = mx;
        __syncthreads();
        float rmx = fmaxf(fmaxf(Pm[m], Pm[64 + m]), fmaxf(Pm[128 + m], Pm[192 + m]));
        float lsum = 0.f;
        #pragma unroll 4
        for (int k = 0; k < 64; k++) {
            float e = __expf(Pt[(qd * 64 + k) * 68 + m] - rmx);
            Pt[(qd * 64 + k) * 68 + m] = e;
            lsum += e;
        }
        Psum[qd * 64 + m] = lsum;
    }
    __syncthreads();

    // Phase B: O[64 x 32] = P @ V; thread owns (d = t&31, 8 tokens mg*8..+7)
    {
        int d = t & 31, mg = t >> 5;
        float o[8] = {};
        #pragma unroll 2
        for (int s = 0; s < 256; s++) {
            float4 pa = *(float4*)&Pt[s * 68 + mg * 8];
            float4 pb = *(float4*)&Pt[s * 68 + mg * 8 + 4];
            float vv = Vs[s * 34 + d];
            o[0] += pa.x * vv; o[1] += pa.y * vv; o[2] += pa.z * vv; o[3] += pa.w * vv;
            o[4] += pb.x * vv; o[5] += pb.y * vv; o[6] += pb.z * vv; o[7] += pb.w * vv;
        }
        #pragma unroll
        for (int i = 0; i < 8; i++) {
            int m = mg * 8 + i;
            float Z = Psum[m] + Psum[64 + m] + Psum[128 + m] + Psum[192 + m];
            ao[((size_t)b * NTOK + n0 + m) * CC + h * HDIM + d] = o[i] / Z;
        }
    }
}

// ---------------- O projection + transpose: Out[b,j,n] = sum_c AO[b,n,c]*W[c,j] + b[j] ----------------
__global__ void oproj_kernel(const float* __restrict__ W, const float* __restrict__ bias,
                             float* __restrict__ Out) {
    __shared__ float As[8 * 132];   // transposed on load, padded stride for conflict-free STS
    __shared__ float Ws[8 * 128];
    const float* Ain = g_scr + OFF_AO;
    int b = blockIdx.z;
    int n0 = blockIdx.y * 128, j0 = blockIdx.x * 128;
    int t = threadIdx.x;
    int tx = t & 15, ty = t >> 4;
    float acc[8][8] = {};
    int lm = t >> 1, lkq = (t & 1) * 4;
    int lk = t >> 5, lc = (t & 31) * 4;
    for (int k0 = 0; k0 < CC; k0 += 8) {
        float4 av = *(const float4*)&Ain[((size_t)b * NTOK + n0 + lm) * CC + k0 + lkq];
        As[(lkq + 0) * 132 + lm] = av.x;
        As[(lkq + 1) * 132 + lm] = av.y;
        As[(lkq + 2) * 132 + lm] = av.z;
        As[(lkq + 3) * 132 + lm] = av.w;
        *(float4*)&Ws[lk * 128 + lc] = *(const float4*)&W[(size_t)(k0 + lk) * CC + j0 + lc];
        __syncthreads();
        #pragma unroll
        for (int kk = 0; kk < 8; kk++) {
            float a[8], w[8];
            *(float4*)&a[0] = *(float4*)&As[kk * 132 + ty * 4];
            *(float4*)&a[4] = *(float4*)&As[kk * 132 + 64 + ty * 4];
            *(float4*)&w[0] = *(float4*)&Ws[kk * 128 + tx * 4];
            *(float4*)&w[4] = *(float4*)&Ws[kk * 128 + 64 + tx * 4];
            #pragma unroll
            for (int i = 0; i < 8; i++)
                #pragma unroll
                for (int j = 0; j < 8; j++) acc[i][j] += a[i] * w[j];
        }
        __syncthreads();
    }
    #pragma unroll
    for (int j = 0; j < 8; j++) {
        int jj = j0 + ((j < 4) ? (tx * 4 + j) : (64 + tx * 4 + j - 4));
        float bv = bias[jj];
        float4 v1 = make_float4(acc[0][j] + bv, acc[1][j] + bv, acc[2][j] + bv, acc[3][j] + bv);
        float4 v2 = make_float4(acc[4][j] + bv, acc[5][j] + bv, acc[6][j] + bv, acc[7][j] + bv);
        float* outp = Out + (size_t)b * CC * NTOK + (size_t)jj * NTOK;
        *(float4*)&outp[n0 + ty * 4]      = v1;
        *(float4*)&outp[n0 + 64 + ty * 4] = v2;
    }
}

// ---------------- launch ----------------
extern "C" void kernel_launch(void* const* d_in, const int* in_sizes, int n_in,
                              void* d_out, int out_size) {
    const float* fv   = (const float*)d_in[0];
    const float* text = (const float*)d_in[1];
    const float* q_w  = (const float*)d_in[2];
    const float* q_b  = (const float*)d_in[3];
    const float* k_w  = (const float*)d_in[4];
    const float* k_b  = (const float*)d_in[5];
    const float* v_w  = (const float*)d_in[6];
    const float* v_b  = (const float*)d_in[7];
    const float* o_w  = (const float*)d_in[8];
    const float* o_b  = (const float*)d_in[9];
    const float* m1_w = (const float*)d_in[10];
    const float* m1_b = (const float*)d_in[11];
    const float* m2_w = (const float*)d_in[12];
    const float* m2_b = (const float*)d_in[13];
    float* out = (float*)d_out;

    float* scr = nullptr;
    cudaGetSymbolAddress((void**)&scr, g_scr);

    init_invf_kernel<<<1, 32>>>();

    // Text side: h1 = gelu(text@m1_w+m1_b); kraw/vraw; phase = h1@m2_w+m2_b
    gemm_rm_kernel<1><<<dim3(4, 8), 256>>>(text, m1_w, m1_b, scr + OFF_H1,    512, 512, 256);
    gemm_rm_kernel<0><<<dim3(4, 8), 256>>>(text, k_w,  k_b,  scr + OFF_KRAW,  512, 512, 256);
    gemm_rm_kernel<0><<<dim3(4, 8), 256>>>(text, v_w,  v_b,  scr + OFF_VRAW,  512, 512, 256);
    gemm_rm_kernel<0><<<dim3(4, 8), 256>>>(scr + OFF_H1, m2_w, m2_b, scr + OFF_PHASE, 512, 256, 256);
    text_rope_kernel<<<256, 256>>>();

    // Visual side
    qproj_kernel<<<dim3(2, 256, 2), 256>>>(fv, q_w, q_b);
    q_rope_kernel<<<32768, 256>>>();

    cudaFuncSetAttribute(attn_kernel, cudaFuncAttributeMaxDynamicSharedMemorySize,
                         ATT_SMEM_FLOATS * (int)sizeof(float));
    attn_kernel<<<dim3(512, 8, 2), 256, ATT_SMEM_FLOATS * sizeof(float)>>>();

    oproj_kernel<<<dim3(2, 256, 2), 256>>>(o_w, o_b, out);
}